// round 1
// baseline (speedup 1.0000x reference)
#include <cuda_runtime.h>
#include <math.h>
#include <stdint.h>

#define NB 2
#define NN 8192
#define NC 128
#define NK 16
#define NP (NB*NN)          // 16384 points total
#define EPSF 1e-5f
#define SA 132              // padded smem row stride (floats), multiple of 4

// ---------------- device scratch (no cudaMalloc allowed) ----------------
__device__ float g_t1[NP*NC];       // s2 * aW1 * Wq * feat   (per point)
__device__ float g_t2[NP*NC];       // s2 * aW1 * Wk * feat   (per point)
__device__ float g_vf[NP*NC];       // Wv * feat              (per point)
__device__ float g_outpre[NP*NC];   // pre-Wout output
__device__ int   g_idx[NP*NK];      // KNN indices (global row ids)

__device__ float g_At[NC*NC];       // transposed [i][o] combined weights
__device__ float g_Bt[NC*NC];
__device__ float g_W3t[NC*NC];
__device__ float g_pW2t[NC*NC];
__device__ float g_aW2t[NC*NC];
__device__ float g_Wvt[NC*NC];
__device__ float g_Woutt[NC*NC];
__device__ float g_cc[NC];          // folded constant for attn pre-activation
__device__ float g_pW1s[NC*3];      // BN1-folded pos MLP first layer
__device__ float g_b1p[NC];

// ---------------- setup: fold BN + compose linear maps ----------------
__global__ void setup_kernel(
    const float* __restrict__ Wq, const float* __restrict__ Wk,
    const float* __restrict__ Wv, const float* __restrict__ pW1,
    const float* __restrict__ pb1, const float* __restrict__ pg,
    const float* __restrict__ pbeta, const float* __restrict__ pmean,
    const float* __restrict__ pvar, const float* __restrict__ pW2,
    const float* __restrict__ pb2, const float* __restrict__ aW1,
    const float* __restrict__ ab1, const float* __restrict__ ag,
    const float* __restrict__ abeta, const float* __restrict__ amean,
    const float* __restrict__ avar, const float* __restrict__ aW2,
    const float* __restrict__ Wout)
{
    __shared__ float arow[NC];
    int o = blockIdx.x;
    int i = threadIdx.x;
    arow[i] = aW1[o*NC + i];
    __syncthreads();
    float s2o = ag[o] * rsqrtf(avar[o] + EPSF);
    float sA = 0.f, sB = 0.f, sW = 0.f;
    #pragma unroll 4
    for (int m = 0; m < NC; ++m) {
        float a = arow[m];
        sA = fmaf(a, Wq[m*NC + i], sA);
        sB = fmaf(a, Wk[m*NC + i], sB);
        sW = fmaf(a, pW2[m*NC + i], sW);
    }
    g_At [i*NC + o] = s2o * sA;
    g_Bt [i*NC + o] = s2o * sB;
    g_W3t[i*NC + o] = s2o * sW;
    g_pW2t[i*NC + o] = pW2[o*NC + i];
    g_aW2t[i*NC + o] = aW2[o*NC + i];
    g_Wvt [i*NC + o] = Wv [o*NC + i];
    g_Woutt[i*NC + o] = Wout[o*NC + i];

    if (o == 0) {
        int c = i;
        float s1 = pg[c] * rsqrtf(pvar[c] + EPSF);
        g_pW1s[c*3+0] = pW1[c*3+0] * s1;
        g_pW1s[c*3+1] = pW1[c*3+1] * s1;
        g_pW1s[c*3+2] = pW1[c*3+2] * s1;
        g_b1p[c] = (pb1[c] - pmean[c]) * s1 + pbeta[c];
        float s2c = ag[c] * rsqrtf(avar[c] + EPSF);
        float c0 = ab1[c];
        for (int m = 0; m < NC; ++m) c0 = fmaf(aW1[c*NC + m], pb2[m], c0);
        g_cc[c] = s2c * c0 + abeta[c] - amean[c] * s2c;
    }
}

// ---------------- KNN: streaming top-16 per query ----------------
__global__ __launch_bounds__(64) void knn_kernel(
    const float* __restrict__ xyz, int* __restrict__ idxo)
{
    int b = blockIdx.y;
    int q = blockIdx.x * 64 + threadIdx.x;
    int base = b * NN;

    float mx = xyz[(size_t)(base+q)*3 + 0];
    float my = xyz[(size_t)(base+q)*3 + 1];
    float mz = xyz[(size_t)(base+q)*3 + 2];
    float sqn = fmaf(mx, mx, fmaf(my, my, mz*mz));

    __shared__ float4 cand[256];

    float bd[NK]; int bi[NK];
    #pragma unroll
    for (int k = 0; k < NK; ++k) { bd[k] = INFINITY; bi[k] = 0x7fffffff; }

    for (int t0 = 0; t0 < NN; t0 += 256) {
        __syncthreads();
        for (int j = threadIdx.x; j < 256; j += 64) {
            int m = t0 + j;
            float x = xyz[(size_t)(base+m)*3 + 0];
            float y = xyz[(size_t)(base+m)*3 + 1];
            float z = xyz[(size_t)(base+m)*3 + 2];
            cand[j] = make_float4(x, y, z, fmaf(x, x, fmaf(y, y, z*z)));
        }
        __syncthreads();
        #pragma unroll 4
        for (int j = 0; j < 256; ++j) {
            float4 c = cand[j];
            float dot = fmaf(mx, c.x, fmaf(my, c.y, mz*c.z));
            float d = sqn + c.w - 2.0f * dot;
            int m = t0 + j;
            if (d < bd[NK-1] || (d == bd[NK-1] && m < bi[NK-1])) {
                bd[NK-1] = d; bi[NK-1] = m;
                #pragma unroll
                for (int s = NK-1; s >= 1; --s) {
                    bool sw = (bd[s] < bd[s-1]) || (bd[s] == bd[s-1] && bi[s] < bi[s-1]);
                    if (sw) {
                        float td = bd[s]; bd[s] = bd[s-1]; bd[s-1] = td;
                        int   ti = bi[s]; bi[s] = bi[s-1]; bi[s-1] = ti;
                    }
                }
            }
        }
    }
    #pragma unroll
    for (int k = 0; k < NK; ++k)
        idxo[(size_t)(base+q)*NK + k] = base + bi[k];
}

// ---------------- shared GEMM inner: acc += AS[128xSA] * Wt^T ----------------
__device__ __forceinline__ void gemm_tile(
    const float* AS, const float* __restrict__ Wt, float* WTs,
    float acc[8][8], int tid, int tx, int ty)
{
    #pragma unroll 1
    for (int k0 = 0; k0 < NC; k0 += 16) {
        __syncthreads();
        int e = tid * 8;
        *(float4*)(WTs + e)     = *(const float4*)(Wt + k0*NC + e);
        *(float4*)(WTs + e + 4) = *(const float4*)(Wt + k0*NC + e + 4);
        __syncthreads();
        #pragma unroll
        for (int kk = 0; kk < 16; ++kk) {
            float wf[8];
            ((float4*)wf)[0] = *(const float4*)(WTs + kk*NC + tx*8);
            ((float4*)wf)[1] = *(const float4*)(WTs + kk*NC + tx*8 + 4);
            float af[8];
            #pragma unroll
            for (int ir = 0; ir < 8; ++ir) af[ir] = AS[(ty*8 + ir)*SA + k0 + kk];
            #pragma unroll
            for (int ir = 0; ir < 8; ++ir)
                #pragma unroll
                for (int io = 0; io < 8; ++io)
                    acc[ir][io] = fmaf(af[ir], wf[io], acc[ir][io]);
        }
    }
}

// ---------------- generic GEMM: out[M,128] = A[M,128] @ Wt(^T stored [i][o]) ----------------
__global__ __launch_bounds__(256) void gemm_rt(
    const float* __restrict__ A, const float* __restrict__ Wt, float* __restrict__ out)
{
    extern __shared__ float sm[];
    float* AS  = sm;               // 128*SA
    float* WTs = AS + NC*SA;       // 16*128

    int tid = threadIdx.x, tx = tid & 15, ty = tid >> 4;
    int p0 = blockIdx.x * 128;

    #pragma unroll
    for (int it = 0; it < 16; ++it) {
        int e = (it*256 + tid) * 4;
        int r = e >> 7, c = e & 127;
        float4 v = *(const float4*)(A + (size_t)(p0 + r)*NC + c);
        *(float4*)(AS + r*SA + c) = v;
    }

    float acc[8][8];
    #pragma unroll
    for (int ir = 0; ir < 8; ++ir)
        #pragma unroll
        for (int io = 0; io < 8; ++io) acc[ir][io] = 0.f;

    gemm_tile(AS, Wt, WTs, acc, tid, tx, ty);

    #pragma unroll
    for (int ir = 0; ir < 8; ++ir) {
        int r = p0 + ty*8 + ir;
        #pragma unroll
        for (int io4 = 0; io4 < 8; io4 += 4) {
            float4 v;
            v.x = acc[ir][io4+0]; v.y = acc[ir][io4+1];
            v.z = acc[ir][io4+2]; v.w = acc[ir][io4+3];
            *(float4*)(out + (size_t)r*NC + tx*8 + io4) = v;
        }
    }
}

// ---------------- fused per-pair pipeline: 8 points / block ----------------
__global__ __launch_bounds__(256) void fused_main(
    const float* __restrict__ xyz, const float* __restrict__ pb2,
    const float* __restrict__ ab2, float* __restrict__ outpre)
{
    extern __shared__ float sm[];
    float* uS  = sm;                 // 128*SA  (u, later reused for logits)
    float* hS  = uS + NC*SA;         // 128*SA
    float* pv  = hS + NC*SA;         // 128*SA  (pos + gathered v)
    float* WTs = pv + NC*SA;         // 16*128
    int*   nid = (int*)(WTs + 16*NC);    // 128
    float* rel = (float*)(nid + NC);     // 128*3

    int tid = threadIdx.x, tx = tid & 15, ty = tid >> 4;
    int p0 = blockIdx.x * 8;

    if (tid < 128) {
        int r = tid;
        int p = p0 + (r >> 4);
        int g = g_idx[(size_t)p*NK + (r & 15)];
        nid[r] = g;
        rel[r*3+0] = xyz[(size_t)g*3+0] - xyz[(size_t)p*3+0];
        rel[r*3+1] = xyz[(size_t)g*3+1] - xyz[(size_t)p*3+1];
        rel[r*3+2] = xyz[(size_t)g*3+2] - xyz[(size_t)p*3+2];
    }
    __syncthreads();

    // u = relu(pW1' * rel + b1')   (BN1 folded)
    {
        int c = tid & 127;
        float w0 = g_pW1s[c*3+0], w1 = g_pW1s[c*3+1], w2 = g_pW1s[c*3+2];
        float bb = g_b1p[c];
        for (int r = (tid >> 7); r < 128; r += 2) {
            float v = fmaf(w0, rel[r*3+0], fmaf(w1, rel[r*3+1], fmaf(w2, rel[r*3+2], bb)));
            uS[r*SA + c] = fmaxf(v, 0.f);
        }
    }

    float acc[8][8];

    // GEMM1a: pre = u @ W3'^T ; h = relu(pre + t1[p] - t2[g] + cc)
    #pragma unroll
    for (int ir = 0; ir < 8; ++ir)
        #pragma unroll
        for (int io = 0; io < 8; ++io) acc[ir][io] = 0.f;
    gemm_tile(uS, g_W3t, WTs, acc, tid, tx, ty);
    #pragma unroll
    for (int ir = 0; ir < 8; ++ir) {
        int r = ty*8 + ir;
        int p = p0 + (r >> 4);
        int g = nid[r];
        #pragma unroll
        for (int io = 0; io < 8; ++io) {
            int o = tx*8 + io;
            float v = acc[ir][io] + g_t1[(size_t)p*NC + o] - g_t2[(size_t)g*NC + o] + g_cc[o];
            hS[r*SA + o] = fmaxf(v, 0.f);
        }
    }

    // GEMM1b: pos = u @ pW2^T + pb2 ; pv = pos + v[g]
    #pragma unroll
    for (int ir = 0; ir < 8; ++ir)
        #pragma unroll
        for (int io = 0; io < 8; ++io) acc[ir][io] = 0.f;
    gemm_tile(uS, g_pW2t, WTs, acc, tid, tx, ty);
    #pragma unroll
    for (int ir = 0; ir < 8; ++ir) {
        int r = ty*8 + ir;
        int g = nid[r];
        #pragma unroll
        for (int io = 0; io < 8; ++io) {
            int o = tx*8 + io;
            pv[r*SA + o] = acc[ir][io] + pb2[o] + g_vf[(size_t)g*NC + o];
        }
    }

    // GEMM2: logits = h @ aW2^T + ab2  -> stored into uS
    #pragma unroll
    for (int ir = 0; ir < 8; ++ir)
        #pragma unroll
        for (int io = 0; io < 8; ++io) acc[ir][io] = 0.f;
    gemm_tile(hS, g_aW2t, WTs, acc, tid, tx, ty);
    #pragma unroll
    for (int ir = 0; ir < 8; ++ir) {
        int r = ty*8 + ir;
        #pragma unroll
        for (int io = 0; io < 8; ++io) {
            int o = tx*8 + io;
            uS[r*SA + o] = acc[ir][io] + ab2[o];
        }
    }
    __syncthreads();

    // per-channel softmax over K neighbors + weighted reduce
    #pragma unroll
    for (int t = tid; t < 8*NC; t += 256) {
        int pp = t >> 7, o = t & 127;
        int rb = pp * NK;
        float m = -INFINITY;
        #pragma unroll
        for (int j = 0; j < NK; ++j) m = fmaxf(m, uS[(rb+j)*SA + o]);
        float s = 0.f, a = 0.f;
        #pragma unroll
        for (int j = 0; j < NK; ++j) {
            float e = __expf(uS[(rb+j)*SA + o] - m);
            s += e;
            a = fmaf(e, pv[(rb+j)*SA + o], a);
        }
        outpre[(size_t)(p0 + pp)*NC + o] = a / s;
    }
}

// ---------------- launch ----------------
#define GEMM_SMEM ((NC*SA + 16*NC) * 4)
#define MAIN_SMEM ((3*NC*SA + 16*NC) * 4 + NC*4 + NC*3*4)

extern "C" void kernel_launch(void* const* d_in, const int* in_sizes, int n_in,
                              void* d_out, int out_size)
{
    const float* xyz   = (const float*)d_in[0];
    const float* feat  = (const float*)d_in[1];
    const float* Wq    = (const float*)d_in[2];
    const float* Wk    = (const float*)d_in[3];
    const float* Wv    = (const float*)d_in[4];
    const float* pW1   = (const float*)d_in[5];
    const float* pb1   = (const float*)d_in[6];
    const float* pg    = (const float*)d_in[7];
    const float* pbeta = (const float*)d_in[8];
    const float* pmean = (const float*)d_in[9];
    const float* pvar  = (const float*)d_in[10];
    const float* pW2   = (const float*)d_in[11];
    const float* pb2   = (const float*)d_in[12];
    const float* aW1   = (const float*)d_in[13];
    const float* ab1   = (const float*)d_in[14];
    const float* ag    = (const float*)d_in[15];
    const float* abeta = (const float*)d_in[16];
    const float* amean = (const float*)d_in[17];
    const float* avar  = (const float*)d_in[18];
    const float* aW2   = (const float*)d_in[19];
    const float* ab2   = (const float*)d_in[20];
    const float* Wout  = (const float*)d_in[21];
    float* out = (float*)d_out;

    void *p_t1, *p_t2, *p_vf, *p_outpre, *p_idx;
    void *p_At, *p_Bt, *p_Wvt, *p_Woutt;
    cudaGetSymbolAddress(&p_t1, g_t1);
    cudaGetSymbolAddress(&p_t2, g_t2);
    cudaGetSymbolAddress(&p_vf, g_vf);
    cudaGetSymbolAddress(&p_outpre, g_outpre);
    cudaGetSymbolAddress(&p_idx, g_idx);
    cudaGetSymbolAddress(&p_At, g_At);
    cudaGetSymbolAddress(&p_Bt, g_Bt);
    cudaGetSymbolAddress(&p_Wvt, g_Wvt);
    cudaGetSymbolAddress(&p_Woutt, g_Woutt);

    cudaFuncSetAttribute(gemm_rt, cudaFuncAttributeMaxDynamicSharedMemorySize, GEMM_SMEM);
    cudaFuncSetAttribute(fused_main, cudaFuncAttributeMaxDynamicSharedMemorySize, MAIN_SMEM);

    setup_kernel<<<NC, NC>>>(Wq, Wk, Wv, pW1, pb1, pg, pbeta, pmean, pvar,
                             pW2, pb2, aW1, ab1, ag, abeta, amean, avar, aW2, Wout);

    knn_kernel<<<dim3(NN/64, NB), 64>>>(xyz, (int*)p_idx);

    gemm_rt<<<NP/128, 256, GEMM_SMEM>>>(feat, (const float*)p_At,  (float*)p_t1);
    gemm_rt<<<NP/128, 256, GEMM_SMEM>>>(feat, (const float*)p_Bt,  (float*)p_t2);
    gemm_rt<<<NP/128, 256, GEMM_SMEM>>>(feat, (const float*)p_Wvt, (float*)p_vf);

    fused_main<<<NP/8, 256, MAIN_SMEM>>>(xyz, pb2, ab2, (float*)p_outpre);

    gemm_rt<<<NP/128, 256, GEMM_SMEM>>>((const float*)p_outpre, (const float*)p_Woutt, out);
}

// round 2
// speedup vs baseline: 1.2255x; 1.2255x over previous
#include <cuda_runtime.h>
#include <math.h>
#include <stdint.h>

#define NB 2
#define NN 8192
#define NC 128
#define NK 16
#define NP (NB*NN)
#define EPSF 1e-5f
#define SA 132              // padded smem row stride (floats)

#define KQ 128              // queries per KNN block
#define KSPLIT 8            // candidate chunks
#define KCH (NN/KSPLIT)     // 1024 candidates per chunk

// ---------------- device scratch ----------------
__device__ float g_t1[NP*NC];
__device__ float g_t2[NP*NC];
__device__ float g_vf[NP*NC];
__device__ float g_outpre[NP*NC];
__device__ int   g_idx[NP*NK];
__device__ float g_pd[NP*KSPLIT*NK];
__device__ int   g_pi[NP*KSPLIT*NK];

__device__ float g_At[NC*NC];
__device__ float g_Bt[NC*NC];
__device__ float g_W3t[NC*NC];
__device__ float g_pW2t[NC*NC];
__device__ float g_aW2t[NC*NC];
__device__ float g_Wvt[NC*NC];
__device__ float g_Woutt[NC*NC];
__device__ float g_cc[NC];
__device__ float g_pW1s[NC*3];
__device__ float g_b1p[NC];

// ---------------- setup: fold BN + compose linear maps ----------------
__global__ void setup_kernel(
    const float* __restrict__ Wq, const float* __restrict__ Wk,
    const float* __restrict__ Wv, const float* __restrict__ pW1,
    const float* __restrict__ pb1, const float* __restrict__ pg,
    const float* __restrict__ pbeta, const float* __restrict__ pmean,
    const float* __restrict__ pvar, const float* __restrict__ pW2,
    const float* __restrict__ pb2, const float* __restrict__ aW1,
    const float* __restrict__ ab1, const float* __restrict__ ag,
    const float* __restrict__ abeta, const float* __restrict__ amean,
    const float* __restrict__ avar, const float* __restrict__ aW2,
    const float* __restrict__ Wout)
{
    __shared__ float arow[NC];
    int o = blockIdx.x;
    int i = threadIdx.x;
    arow[i] = aW1[o*NC + i];
    __syncthreads();
    float s2o = ag[o] * rsqrtf(avar[o] + EPSF);
    float sA = 0.f, sB = 0.f, sW = 0.f;
    #pragma unroll 4
    for (int m = 0; m < NC; ++m) {
        float a = arow[m];
        sA = fmaf(a, Wq[m*NC + i], sA);
        sB = fmaf(a, Wk[m*NC + i], sB);
        sW = fmaf(a, pW2[m*NC + i], sW);
    }
    g_At [i*NC + o] = s2o * sA;
    g_Bt [i*NC + o] = s2o * sB;
    g_W3t[i*NC + o] = s2o * sW;
    g_pW2t[i*NC + o] = pW2[o*NC + i];
    g_aW2t[i*NC + o] = aW2[o*NC + i];
    g_Wvt [i*NC + o] = Wv [o*NC + i];
    g_Woutt[i*NC + o] = Wout[o*NC + i];

    if (o == 0) {
        int c = i;
        float s1 = pg[c] * rsqrtf(pvar[c] + EPSF);
        g_pW1s[c*3+0] = pW1[c*3+0] * s1;
        g_pW1s[c*3+1] = pW1[c*3+1] * s1;
        g_pW1s[c*3+2] = pW1[c*3+2] * s1;
        g_b1p[c] = (pb1[c] - pmean[c]) * s1 + pbeta[c];
        float s2c = ag[c] * rsqrtf(avar[c] + EPSF);
        float c0 = ab1[c];
        for (int m = 0; m < NC; ++m) c0 = fmaf(aW1[c*NC + m], pb2[m], c0);
        g_cc[c] = s2c * c0 + abeta[c] - amean[c] * s2c;
    }
}

// ---------------- KNN stage 1: per-chunk top-16 ----------------
__global__ __launch_bounds__(KQ) void knn_part(
    const float* __restrict__ xyz, float* __restrict__ pd, int* __restrict__ pi)
{
    int qg = blockIdx.x * KQ + threadIdx.x;
    int base = (qg / NN) * NN;
    int c0 = base + blockIdx.y * KCH;

    float mx = xyz[(size_t)qg*3 + 0];
    float my = xyz[(size_t)qg*3 + 1];
    float mz = xyz[(size_t)qg*3 + 2];
    float sqn = fmaf(mx, mx, fmaf(my, my, mz*mz));

    __shared__ float4 cand[256];

    float bd[NK]; int bi[NK];
    #pragma unroll
    for (int k = 0; k < NK; ++k) { bd[k] = INFINITY; bi[k] = 0x7fffffff; }

    for (int t0 = 0; t0 < KCH; t0 += 256) {
        __syncthreads();
        #pragma unroll
        for (int j = threadIdx.x; j < 256; j += KQ) {
            int m = c0 + t0 + j;
            float x = xyz[(size_t)m*3 + 0];
            float y = xyz[(size_t)m*3 + 1];
            float z = xyz[(size_t)m*3 + 2];
            cand[j] = make_float4(x, y, z, fmaf(x, x, fmaf(y, y, z*z)));
        }
        __syncthreads();
        #pragma unroll 4
        for (int j = 0; j < 256; ++j) {
            float4 c = cand[j];
            float dot = fmaf(mx, c.x, fmaf(my, c.y, mz*c.z));
            float d = sqn + c.w - 2.0f * dot;
            int m = t0 + j;
            if (d < bd[NK-1] || (d == bd[NK-1] && m < bi[NK-1])) {
                bd[NK-1] = d; bi[NK-1] = m;
                #pragma unroll
                for (int s = NK-1; s >= 1; --s) {
                    bool sw = (bd[s] < bd[s-1]) || (bd[s] == bd[s-1] && bi[s] < bi[s-1]);
                    if (sw) {
                        float td = bd[s]; bd[s] = bd[s-1]; bd[s-1] = td;
                        int   ti = bi[s]; bi[s] = bi[s-1]; bi[s-1] = ti;
                    }
                }
            }
        }
    }
    size_t ob = (size_t)qg * (KSPLIT*NK) + blockIdx.y * NK;
    #pragma unroll
    for (int k = 0; k < NK; ++k) {
        pd[ob + k] = bd[k];
        pi[ob + k] = c0 + bi[k];   // global row id
    }
}

// ---------------- KNN stage 2: merge 8 sorted lists ----------------
__global__ __launch_bounds__(128) void knn_merge(
    const float* __restrict__ pd, const int* __restrict__ pi, int* __restrict__ idxo)
{
    int q = blockIdx.x * 128 + threadIdx.x;
    float bd[NK]; int bi[NK];
    #pragma unroll
    for (int k = 0; k < NK; ++k) { bd[k] = INFINITY; bi[k] = 0x7fffffff; }
    size_t ib = (size_t)q * (KSPLIT*NK);
    for (int j = 0; j < KSPLIT*NK; ++j) {
        float d = pd[ib + j];
        int   m = pi[ib + j];
        if (d < bd[NK-1] || (d == bd[NK-1] && m < bi[NK-1])) {
            bd[NK-1] = d; bi[NK-1] = m;
            #pragma unroll
            for (int s = NK-1; s >= 1; --s) {
                bool sw = (bd[s] < bd[s-1]) || (bd[s] == bd[s-1] && bi[s] < bi[s-1]);
                if (sw) {
                    float td = bd[s]; bd[s] = bd[s-1]; bd[s-1] = td;
                    int   ti = bi[s]; bi[s] = bi[s-1]; bi[s-1] = ti;
                }
            }
        }
    }
    #pragma unroll
    for (int k = 0; k < NK; ++k)
        idxo[(size_t)q*NK + k] = bi[k];
}

// ---------------- fused feature projections: t1/t2/vf ----------------
__global__ __launch_bounds__(512) void gemm3(
    const float* __restrict__ A, float* __restrict__ t1,
    float* __restrict__ t2, float* __restrict__ vf)
{
    extern __shared__ float sm[];
    float* AS  = sm;               // 128*SA
    float* WT0 = AS + NC*SA;       // 16*128
    float* WT1 = WT0 + 16*NC;      // 16*128

    int tid = threadIdx.x, tx = tid & 15, ty = tid >> 4;  // ty 0..31
    int p0 = blockIdx.x * 128;

    #pragma unroll
    for (int it = 0; it < 8; ++it) {
        int e = (it*512 + tid) * 4;
        int r = e >> 7, c = e & 127;
        *(float4*)(AS + r*SA + c) = *(const float4*)(A + (size_t)(p0 + r)*NC + c);
    }

    float acc1[4][8], acc2[4][8];
    #pragma unroll
    for (int ir = 0; ir < 4; ++ir)
        #pragma unroll
        for (int io = 0; io < 8; ++io) { acc1[ir][io] = 0.f; acc2[ir][io] = 0.f; }

    // pass 1: t1 (At), t2 (Bt)
    #pragma unroll 1
    for (int k0 = 0; k0 < NC; k0 += 16) {
        __syncthreads();
        int e = tid * 4;
        *(float4*)(WT0 + e) = *(const float4*)(g_At + k0*NC + e);
        *(float4*)(WT1 + e) = *(const float4*)(g_Bt + k0*NC + e);
        __syncthreads();
        #pragma unroll
        for (int kk = 0; kk < 16; ++kk) {
            float wa[8], wb[8], af[4];
            ((float4*)wa)[0] = *(float4*)(WT0 + kk*NC + tx*8);
            ((float4*)wa)[1] = *(float4*)(WT0 + kk*NC + tx*8 + 4);
            ((float4*)wb)[0] = *(float4*)(WT1 + kk*NC + tx*8);
            ((float4*)wb)[1] = *(float4*)(WT1 + kk*NC + tx*8 + 4);
            #pragma unroll
            for (int ir = 0; ir < 4; ++ir) af[ir] = AS[(ty*4 + ir)*SA + k0 + kk];
            #pragma unroll
            for (int ir = 0; ir < 4; ++ir)
                #pragma unroll
                for (int io = 0; io < 8; ++io) {
                    acc1[ir][io] = fmaf(af[ir], wa[io], acc1[ir][io]);
                    acc2[ir][io] = fmaf(af[ir], wb[io], acc2[ir][io]);
                }
        }
    }
    #pragma unroll
    for (int ir = 0; ir < 4; ++ir) {
        int r = p0 + ty*4 + ir;
        #pragma unroll
        for (int q = 0; q < 2; ++q) {
            float4 v1, v2;
            v1.x = acc1[ir][q*4+0]; v1.y = acc1[ir][q*4+1]; v1.z = acc1[ir][q*4+2]; v1.w = acc1[ir][q*4+3];
            v2.x = acc2[ir][q*4+0]; v2.y = acc2[ir][q*4+1]; v2.z = acc2[ir][q*4+2]; v2.w = acc2[ir][q*4+3];
            *(float4*)(t1 + (size_t)r*NC + tx*8 + q*4) = v1;
            *(float4*)(t2 + (size_t)r*NC + tx*8 + q*4) = v2;
        }
    }

    // pass 2: vf (Wvt)
    #pragma unroll
    for (int ir = 0; ir < 4; ++ir)
        #pragma unroll
        for (int io = 0; io < 8; ++io) acc1[ir][io] = 0.f;
    #pragma unroll 1
    for (int k0 = 0; k0 < NC; k0 += 16) {
        __syncthreads();
        int e = tid * 4;
        *(float4*)(WT0 + e) = *(const float4*)(g_Wvt + k0*NC + e);
        __syncthreads();
        #pragma unroll
        for (int kk = 0; kk < 16; ++kk) {
            float wa[8], af[4];
            ((float4*)wa)[0] = *(float4*)(WT0 + kk*NC + tx*8);
            ((float4*)wa)[1] = *(float4*)(WT0 + kk*NC + tx*8 + 4);
            #pragma unroll
            for (int ir = 0; ir < 4; ++ir) af[ir] = AS[(ty*4 + ir)*SA + k0 + kk];
            #pragma unroll
            for (int ir = 0; ir < 4; ++ir)
                #pragma unroll
                for (int io = 0; io < 8; ++io)
                    acc1[ir][io] = fmaf(af[ir], wa[io], acc1[ir][io]);
        }
    }
    #pragma unroll
    for (int ir = 0; ir < 4; ++ir) {
        int r = p0 + ty*4 + ir;
        #pragma unroll
        for (int q = 0; q < 2; ++q) {
            float4 v1;
            v1.x = acc1[ir][q*4+0]; v1.y = acc1[ir][q*4+1]; v1.z = acc1[ir][q*4+2]; v1.w = acc1[ir][q*4+3];
            *(float4*)(vf + (size_t)r*NC + tx*8 + q*4) = v1;
        }
    }
}

// ---------------- fused per-pair pipeline: 8 points / block, 512 threads ----------------
__global__ __launch_bounds__(512) void fused_main(
    const float* __restrict__ xyz, const float* __restrict__ pb2,
    const float* __restrict__ ab2, float* __restrict__ outpre)
{
    extern __shared__ float sm[];
    float* uS  = sm;                 // 128*SA (u, later logits)
    float* hS  = uS + NC*SA;
    float* pv  = hS + NC*SA;
    float* WT0 = pv + NC*SA;         // 16*128
    float* WT1 = WT0 + 16*NC;        // 16*128
    int*   nid = (int*)(WT1 + 16*NC);    // 128
    float* rel = (float*)(nid + NC);     // 128*3

    int tid = threadIdx.x, tx = tid & 15, ty = tid >> 4;  // ty 0..31
    int p0 = blockIdx.x * 8;

    if (tid < 128) {
        int r = tid;
        int p = p0 + (r >> 4);
        int g = g_idx[(size_t)p*NK + (r & 15)];
        nid[r] = g;
        rel[r*3+0] = xyz[(size_t)g*3+0] - xyz[(size_t)p*3+0];
        rel[r*3+1] = xyz[(size_t)g*3+1] - xyz[(size_t)p*3+1];
        rel[r*3+2] = xyz[(size_t)g*3+2] - xyz[(size_t)p*3+2];
    }
    __syncthreads();

    // u = relu(pW1' * rel + b1')
    {
        int c = tid & 127;
        int r0 = tid >> 7;   // 0..3
        float w0 = g_pW1s[c*3+0], w1 = g_pW1s[c*3+1], w2 = g_pW1s[c*3+2];
        float bb = g_b1p[c];
        #pragma unroll
        for (int r = r0; r < 128; r += 4) {
            float v = fmaf(w0, rel[r*3+0], fmaf(w1, rel[r*3+1], fmaf(w2, rel[r*3+2], bb)));
            uS[r*SA + c] = fmaxf(v, 0.f);
        }
    }

    float acc1[4][8], acc2[4][8];
    #pragma unroll
    for (int ir = 0; ir < 4; ++ir)
        #pragma unroll
        for (int io = 0; io < 8; ++io) { acc1[ir][io] = 0.f; acc2[ir][io] = 0.f; }

    // fused GEMM1a (W3') + GEMM1b (pW2), shared A = u
    #pragma unroll 1
    for (int k0 = 0; k0 < NC; k0 += 16) {
        __syncthreads();
        int e = tid * 4;
        *(float4*)(WT0 + e) = *(const float4*)(g_W3t  + k0*NC + e);
        *(float4*)(WT1 + e) = *(const float4*)(g_pW2t + k0*NC + e);
        __syncthreads();
        #pragma unroll
        for (int kk = 0; kk < 16; ++kk) {
            float wa[8], wb[8], af[4];
            ((float4*)wa)[0] = *(float4*)(WT0 + kk*NC + tx*8);
            ((float4*)wa)[1] = *(float4*)(WT0 + kk*NC + tx*8 + 4);
            ((float4*)wb)[0] = *(float4*)(WT1 + kk*NC + tx*8);
            ((float4*)wb)[1] = *(float4*)(WT1 + kk*NC + tx*8 + 4);
            #pragma unroll
            for (int ir = 0; ir < 4; ++ir) af[ir] = uS[(ty*4 + ir)*SA + k0 + kk];
            #pragma unroll
            for (int ir = 0; ir < 4; ++ir)
                #pragma unroll
                for (int io = 0; io < 8; ++io) {
                    acc1[ir][io] = fmaf(af[ir], wa[io], acc1[ir][io]);
                    acc2[ir][io] = fmaf(af[ir], wb[io], acc2[ir][io]);
                }
        }
    }

    // epilogue: h = relu(acc1 + t1[p] - t2[g] + cc) ; pv = acc2 + pb2 + vf[g]
    {
        float4 ccA = *(const float4*)(g_cc + tx*8);
        float4 ccB = *(const float4*)(g_cc + tx*8 + 4);
        float4 pbA = *(const float4*)(pb2 + tx*8);
        float4 pbB = *(const float4*)(pb2 + tx*8 + 4);
        float cc8[8] = {ccA.x,ccA.y,ccA.z,ccA.w,ccB.x,ccB.y,ccB.z,ccB.w};
        float pb8[8] = {pbA.x,pbA.y,pbA.z,pbA.w,pbB.x,pbB.y,pbB.z,pbB.w};
        #pragma unroll
        for (int ir = 0; ir < 4; ++ir) {
            int r = ty*4 + ir;
            int p = p0 + (r >> 4);
            int g = nid[r];
            float4 t1A = *(const float4*)(g_t1 + (size_t)p*NC + tx*8);
            float4 t1B = *(const float4*)(g_t1 + (size_t)p*NC + tx*8 + 4);
            float4 t2A = *(const float4*)(g_t2 + (size_t)g*NC + tx*8);
            float4 t2B = *(const float4*)(g_t2 + (size_t)g*NC + tx*8 + 4);
            float4 vfA = *(const float4*)(g_vf + (size_t)g*NC + tx*8);
            float4 vfB = *(const float4*)(g_vf + (size_t)g*NC + tx*8 + 4);
            float t18[8] = {t1A.x,t1A.y,t1A.z,t1A.w,t1B.x,t1B.y,t1B.z,t1B.w};
            float t28[8] = {t2A.x,t2A.y,t2A.z,t2A.w,t2B.x,t2B.y,t2B.z,t2B.w};
            float vf8[8] = {vfA.x,vfA.y,vfA.z,vfA.w,vfB.x,vfB.y,vfB.z,vfB.w};
            #pragma unroll
            for (int io = 0; io < 8; ++io) {
                int o = tx*8 + io;
                hS[r*SA + o] = fmaxf(acc1[ir][io] + t18[io] - t28[io] + cc8[io], 0.f);
                pv[r*SA + o] = acc2[ir][io] + pb8[io] + vf8[io];
            }
        }
    }

    // GEMM2: logits = h @ aW2^T + ab2 -> uS
    #pragma unroll
    for (int ir = 0; ir < 4; ++ir)
        #pragma unroll
        for (int io = 0; io < 8; ++io) acc1[ir][io] = 0.f;
    #pragma unroll 1
    for (int k0 = 0; k0 < NC; k0 += 16) {
        __syncthreads();
        int e = tid * 4;
        *(float4*)(WT0 + e) = *(const float4*)(g_aW2t + k0*NC + e);
        __syncthreads();
        #pragma unroll
        for (int kk = 0; kk < 16; ++kk) {
            float wa[8], af[4];
            ((float4*)wa)[0] = *(float4*)(WT0 + kk*NC + tx*8);
            ((float4*)wa)[1] = *(float4*)(WT0 + kk*NC + tx*8 + 4);
            #pragma unroll
            for (int ir = 0; ir < 4; ++ir) af[ir] = hS[(ty*4 + ir)*SA + k0 + kk];
            #pragma unroll
            for (int ir = 0; ir < 4; ++ir)
                #pragma unroll
                for (int io = 0; io < 8; ++io)
                    acc1[ir][io] = fmaf(af[ir], wa[io], acc1[ir][io]);
        }
    }
    __syncthreads();   // all reads of uS (as u) done before overwrite below
    {
        float4 abA = *(const float4*)(ab2 + tx*8);
        float4 abB = *(const float4*)(ab2 + tx*8 + 4);
        float ab8[8] = {abA.x,abA.y,abA.z,abA.w,abB.x,abB.y,abB.z,abB.w};
        #pragma unroll
        for (int ir = 0; ir < 4; ++ir) {
            int r = ty*4 + ir;
            #pragma unroll
            for (int io = 0; io < 8; ++io)
                uS[r*SA + tx*8 + io] = acc1[ir][io] + ab8[io];
        }
    }
    __syncthreads();

    // per-channel softmax over K + weighted reduce
    #pragma unroll
    for (int t = tid; t < 8*NC; t += 512) {
        int pp = t >> 7, o = t & 127;
        int rb = pp * NK;
        float m = -INFINITY;
        #pragma unroll
        for (int j = 0; j < NK; ++j) m = fmaxf(m, uS[(rb+j)*SA + o]);
        float s = 0.f, a = 0.f;
        #pragma unroll
        for (int j = 0; j < NK; ++j) {
            float e = __expf(uS[(rb+j)*SA + o] - m);
            s += e;
            a = fmaf(e, pv[(rb+j)*SA + o], a);
        }
        outpre[(size_t)(p0 + pp)*NC + o] = a / s;
    }
}

// ---------------- final GEMM (Wout) ----------------
__device__ __forceinline__ void gemm_tile(
    const float* AS, const float* __restrict__ Wt, float* WTs,
    float acc[8][8], int tid, int tx, int ty)
{
    #pragma unroll 1
    for (int k0 = 0; k0 < NC; k0 += 16) {
        __syncthreads();
        int e = tid * 8;
        *(float4*)(WTs + e)     = *(const float4*)(Wt + k0*NC + e);
        *(float4*)(WTs + e + 4) = *(const float4*)(Wt + k0*NC + e + 4);
        __syncthreads();
        #pragma unroll
        for (int kk = 0; kk < 16; ++kk) {
            float wf[8];
            ((float4*)wf)[0] = *(const float4*)(WTs + kk*NC + tx*8);
            ((float4*)wf)[1] = *(const float4*)(WTs + kk*NC + tx*8 + 4);
            float af[8];
            #pragma unroll
            for (int ir = 0; ir < 8; ++ir) af[ir] = AS[(ty*8 + ir)*SA + k0 + kk];
            #pragma unroll
            for (int ir = 0; ir < 8; ++ir)
                #pragma unroll
                for (int io = 0; io < 8; ++io)
                    acc[ir][io] = fmaf(af[ir], wf[io], acc[ir][io]);
        }
    }
}

__global__ __launch_bounds__(256) void gemm_rt(
    const float* __restrict__ A, const float* __restrict__ Wt, float* __restrict__ out)
{
    extern __shared__ float sm[];
    float* AS  = sm;
    float* WTs = AS + NC*SA;

    int tid = threadIdx.x, tx = tid & 15, ty = tid >> 4;
    int p0 = blockIdx.x * 128;

    #pragma unroll
    for (int it = 0; it < 16; ++it) {
        int e = (it*256 + tid) * 4;
        int r = e >> 7, c = e & 127;
        *(float4*)(AS + r*SA + c) = *(const float4*)(A + (size_t)(p0 + r)*NC + c);
    }

    float acc[8][8];
    #pragma unroll
    for (int ir = 0; ir < 8; ++ir)
        #pragma unroll
        for (int io = 0; io < 8; ++io) acc[ir][io] = 0.f;

    gemm_tile(AS, Wt, WTs, acc, tid, tx, ty);

    #pragma unroll
    for (int ir = 0; ir < 8; ++ir) {
        int r = p0 + ty*8 + ir;
        #pragma unroll
        for (int io4 = 0; io4 < 8; io4 += 4) {
            float4 v;
            v.x = acc[ir][io4+0]; v.y = acc[ir][io4+1];
            v.z = acc[ir][io4+2]; v.w = acc[ir][io4+3];
            *(float4*)(out + (size_t)r*NC + tx*8 + io4) = v;
        }
    }
}

// ---------------- launch ----------------
#define GEMM_SMEM  ((NC*SA + 16*NC) * 4)
#define GEMM3_SMEM ((NC*SA + 2*16*NC) * 4)
#define MAIN_SMEM  ((3*NC*SA + 2*16*NC) * 4 + NC*4 + NC*3*4)

extern "C" void kernel_launch(void* const* d_in, const int* in_sizes, int n_in,
                              void* d_out, int out_size)
{
    const float* xyz   = (const float*)d_in[0];
    const float* feat  = (const float*)d_in[1];
    const float* Wq    = (const float*)d_in[2];
    const float* Wk    = (const float*)d_in[3];
    const float* Wv    = (const float*)d_in[4];
    const float* pW1   = (const float*)d_in[5];
    const float* pb1   = (const float*)d_in[6];
    const float* pg    = (const float*)d_in[7];
    const float* pbeta = (const float*)d_in[8];
    const float* pmean = (const float*)d_in[9];
    const float* pvar  = (const float*)d_in[10];
    const float* pW2   = (const float*)d_in[11];
    const float* pb2   = (const float*)d_in[12];
    const float* aW1   = (const float*)d_in[13];
    const float* ab1   = (const float*)d_in[14];
    const float* ag    = (const float*)d_in[15];
    const float* abeta = (const float*)d_in[16];
    const float* amean = (const float*)d_in[17];
    const float* avar  = (const float*)d_in[18];
    const float* aW2   = (const float*)d_in[19];
    const float* ab2   = (const float*)d_in[20];
    const float* Wout  = (const float*)d_in[21];
    float* out = (float*)d_out;

    void *p_t1, *p_t2, *p_vf, *p_outpre, *p_idx, *p_pd, *p_pi, *p_Woutt;
    cudaGetSymbolAddress(&p_t1, g_t1);
    cudaGetSymbolAddress(&p_t2, g_t2);
    cudaGetSymbolAddress(&p_vf, g_vf);
    cudaGetSymbolAddress(&p_outpre, g_outpre);
    cudaGetSymbolAddress(&p_idx, g_idx);
    cudaGetSymbolAddress(&p_pd, g_pd);
    cudaGetSymbolAddress(&p_pi, g_pi);
    cudaGetSymbolAddress(&p_Woutt, g_Woutt);

    cudaFuncSetAttribute(gemm_rt,    cudaFuncAttributeMaxDynamicSharedMemorySize, GEMM_SMEM);
    cudaFuncSetAttribute(gemm3,      cudaFuncAttributeMaxDynamicSharedMemorySize, GEMM3_SMEM);
    cudaFuncSetAttribute(fused_main, cudaFuncAttributeMaxDynamicSharedMemorySize, MAIN_SMEM);

    setup_kernel<<<NC, NC>>>(Wq, Wk, Wv, pW1, pb1, pg, pbeta, pmean, pvar,
                             pW2, pb2, aW1, ab1, ag, abeta, amean, avar, aW2, Wout);

    knn_part<<<dim3(NP/KQ, KSPLIT), KQ>>>(xyz, (float*)p_pd, (int*)p_pi);
    knn_merge<<<NP/128, 128>>>((const float*)p_pd, (const int*)p_pi, (int*)p_idx);

    gemm3<<<NP/128, 512, GEMM3_SMEM>>>(feat, (float*)p_t1, (float*)p_t2, (float*)p_vf);

    fused_main<<<NP/8, 512, MAIN_SMEM>>>(xyz, pb2, ab2, (float*)p_outpre);

    gemm_rt<<<NP/128, 256, GEMM_SMEM>>>((const float*)p_outpre, (const float*)p_Woutt, out);
}